// round 13
// baseline (speedup 1.0000x reference)
#include <cuda_runtime.h>
#include <cstdint>
#include <cstddef>

#define T_TOT 8192
#define MULT  512
#define OUTW  8192
#define VROW  1536

#define BT 32
#define BW 128
#define NTHR 256
#define NITER 16                      // k-chunk = 32

#define A_STAGE_W (3*16*64)           // 3072 words (3 planes x 16 pairlines x 64)
#define B_STAGE_W (64*64)             // 4096 words (64 pairlines x 64)
#define STAGE_W   (A_STAGE_W + B_STAGE_W)   // 7168
#define NSTAGE 3
#define DYN_SMEM  (NSTAGE*STAGE_W*4)  // 86016 bytes -> 2 CTAs/SM

#define VPLANE (T_TOT*MULT)           // 4096 pairlines x 1024 words

// ---- scratch (static device globals: allowed; no runtime allocation)
// Layout: plane i / pairline P / chunk C / word w  ->  i*VPLANE + P*1024 + C*64 + w
//   pairline(row) = (row>>4)*8 + (row&7); p = (row>>3)&1
//   word(u32,row) = (4*((((u32>>3) + (row&7)) & 3)) + (u32&3))*4 + 2*((u32>>2)&1) + p
__device__ uint32_t g_Vd[3u * VPLANE];
__device__ uint32_t g_W1t[MULT * MULT];

static __device__ __forceinline__ uint32_t smem_u32(const void* p) {
    uint32_t r;
    asm("{ .reg .u64 t; cvta.to.shared.u64 t, %1; cvt.u32.u64 %0, t; }" : "=r"(r) : "l"(p));
    return r;
}
static __device__ __forceinline__ uint32_t f2tf(float x) {
    uint32_t r; asm("cvt.rna.tf32.f32 %0, %1;" : "=r"(r) : "f"(x)); return r;
}
static __device__ __forceinline__ void cpa16(uint32_t dst, const void* src) {
    asm volatile("cp.async.cg.shared.global [%0], [%1], 16;" :: "r"(dst), "l"(src));
}
static __device__ __forceinline__ void mma8(float* c, const uint32_t* a, const uint32_t* b) {
    asm volatile(
        "mma.sync.aligned.m16n8k8.row.col.f32.tf32.tf32.f32 "
        "{%0,%1,%2,%3},{%4,%5,%6,%7},{%8,%9},{%0,%1,%2,%3};\n"
        : "+f"(c[0]), "+f"(c[1]), "+f"(c[2]), "+f"(c[3])
        : "r"(a[0]), "r"(a[1]), "r"(a[2]), "r"(a[3]),
          "r"(b[0]), "r"(b[1]));
}

// ---- merged pre-kernel: blocks [0,4096) = V token-pairs; [4096,4224) = W1 tiles
__global__ void __launch_bounds__(512, 2)
pre_all(const float* __restrict__ V, const float* __restrict__ W1) {
    const int tid = threadIdx.x;

    if (blockIdx.x < 4096) {
        // ---- V: one token-pair per block; thread = one u (0..511)
        const int P  = blockIdx.x;
        const int t1 = (P >> 3) * 16 + (P & 7);    // p=0 row
        const int u  = tid;
        const float* s1 = V + (size_t)t1 * VROW + 3 * u;
        const float* s2 = s1 + 8 * VROW;           // t2 = t1 + 8 (p=1)
        const int u32 = u & 31;
        const int w2 = (4 * ((((u32 >> 3) + (P & 7)) & 3)) + (u32 & 3)) * 4
                     + 2 * ((u32 >> 2) & 1);
        const size_t o = (size_t)P * 1024 + (u >> 5) * 64 + w2;
        const float a0 = s1[0], a1 = s1[1], a2 = s1[2];
        const float b0 = s2[0], b1 = s2[1], b2 = s2[2];
        *(uint2*)&g_Vd[o]              = make_uint2(f2tf(a0), f2tf(b0));
        *(uint2*)&g_Vd[o + VPLANE]     = make_uint2(f2tf(a1), f2tf(b1));
        *(uint2*)&g_Vd[o + 2 * VPLANE] = make_uint2(f2tf(a2), f2tf(b2));
    } else {
        // ---- W: W1 [u][n] -> g_W1t, 2 tiles (32x32) per block
        __shared__ float wt[2][32][33];
        const int h = tid >> 8;
        const int t256 = tid & 255;
        const int tx = t256 & 31, ty = t256 >> 5;  // (32, 8)
        const int tile = (blockIdx.x - 4096) * 2 + h;
        const int bn = (tile & 15) * 32, bu = (tile >> 4) * 32;
#pragma unroll
        for (int j = 0; j < 32; j += 8)
            wt[h][ty + j][tx] = W1[(size_t)(bu + ty + j) * MULT + bn + tx];
        __syncthreads();
#pragma unroll
        for (int j = 0; j < 32; j += 8) {
            const int n = bn + ty + j;
            const int u = bu + tx;
            const int u32 = u & 31;
            const int w = (4 * ((((u32 >> 3) + (n & 7)) & 3)) + (u32 & 3)) * 4
                        + 2 * ((u32 >> 2) & 1) + ((n >> 3) & 1);
            const size_t o = (size_t)((n >> 4) * 8 + (n & 7)) * 1024 + (u >> 5) * 64 + w;
            g_W1t[o] = f2tf(wt[h][tx][ty + j]);
        }
    }
}

// ---- main fused kernel: CTA 32x128, warp 16x32x3, LDS.128 fragments, 2 CTAs/SM
__global__ void __launch_bounds__(NTHR, 2)
fused(const float* __restrict__ S, const float* __restrict__ W0,
      float* __restrict__ out)
{
    extern __shared__ uint32_t dsm[];
    __shared__ float sS[96];
    __shared__ float sW0[384];

    const int tid  = threadIdx.x;
    const int lane = tid & 31;
    const int wid  = tid >> 5;
    const int q  = lane >> 2;          // 0..7
    const int rr = lane & 3;           // 0..3
    const int warp_t = wid >> 2;       // 0..1 -> rows warp_t*16
    const int warp_w = wid & 3;        // 0..3 -> cols warp_w*32
    const int bx = blockIdx.x, by = blockIdx.y;
    const int tt0 = by * BT, w0 = bx * BW;

    if (tid < 96)  sS[tid]  = S[(size_t)tt0 * 3 + tid];
    sW0[tid] = W0[(tid >> 7) * 512 + w0 + (tid & 127)];
    if (tid < 128) sW0[256 + tid] = W0[1024 + w0 + tid];

    // ---- staging addresses (loop-invariant); chunk advance = +64 words
    const uint32_t smem0 = smem_u32(dsm);
    const int pl = tid >> 4, un4 = (tid & 15) * 4;
    uint32_t aDst[3]; const uint32_t* aSrc[3];
#pragma unroll
    for (int s = 0; s < 3; s++) {
        aDst[s] = smem0 + (tid + s * 256) * 16;
        aSrc[s] = g_Vd + (size_t)s * VPLANE + (size_t)(by * 16 + pl) * 1024 + un4;
    }
    uint32_t bDst[4]; const uint32_t* bSrc[4];
#pragma unroll
    for (int s = 0; s < 4; s++) {
        bDst[s] = smem0 + (A_STAGE_W + (tid + s * 256) * 4) * 4;
        bSrc[s] = g_W1t + (size_t)(bx * 64 + pl + s * 16) * 1024 + un4;
    }

#define STAGE(K, BUF) do {                                                  \
        const uint32_t off_ = (BUF) * (STAGE_W * 4);                        \
        const int kw_ = (K) * 64;                                           \
        _Pragma("unroll")                                                   \
        for (int s_ = 0; s_ < 3; s_++) cpa16(aDst[s_] + off_, aSrc[s_] + kw_); \
        _Pragma("unroll")                                                   \
        for (int s_ = 0; s_ < 4; s_++) cpa16(bDst[s_] + off_, bSrc[s_] + kw_); \
        asm volatile("cp.async.commit_group;" ::: "memory");                \
    } while (0)

    float acc[3][4][4];
#pragma unroll
    for (int i = 0; i < 3; i++)
#pragma unroll
        for (int n = 0; n < 4; n++)
#pragma unroll
            for (int r = 0; r < 4; r++) acc[i][n][r] = 0.f;

    STAGE(0, 0);
    STAGE(1, 1);

    float4* out4 = reinterpret_cast<float4*>(out);
    const float4 zq = make_float4(0.f, 0.f, 0.f, 0.f);

    // loop-invariant fragment addressing
    const int abase = (warp_t * 8 + q) * 64;   // A pairline base (within plane)
    const int bbase = (warp_w * 16 + q) * 64;  // B pairline base (nt2=0)
    int koff[4];
#pragma unroll
    for (int g = 0; g < 4; g++) koff[g] = 16 * ((g + q) & 3) + 4 * rr;

    float4* zpb = out4 + (size_t)(tt0 + (tid >> 7)) * 2048 + 512 + 384 * bx
                + (tid & 127) * 3;

    int buf = 0;
    for (int it = 0; it < NITER; ++it) {
        if (it == NITER - 1) asm volatile("cp.async.wait_group 0;" ::: "memory");
        else                 asm volatile("cp.async.wait_group 1;" ::: "memory");
        __syncthreads();

        if (it + 2 < NITER) {
            const int nb = (buf + 2 >= NSTAGE) ? buf + 2 - NSTAGE : buf + 2;
            STAGE(it + 2, nb);
        }

        // ---- stream the exact-zero block (2 rows x 384 quads per iter)
        {
            float4* zp = zpb + (size_t)it * 4096;
            zp[0] = zq; zp[1] = zq; zp[2] = zq;
        }

        // ---- compute 4 k8-steps: 5 LDS.128 + 12 MMA per g, conflict-free
        const uint32_t* sA = dsm + buf * STAGE_W;
        const uint32_t* sB = sA + A_STAGE_W;
#pragma unroll
        for (int g = 0; g < 4; g++) {
            const int ko = koff[g];
            const uint4 bq0 = *reinterpret_cast<const uint4*>(&sB[bbase + ko]);
            const uint4 bq1 = *reinterpret_cast<const uint4*>(&sB[bbase + 512 + ko]);
            // quad order = [n_k, n8_k, n_k4, n8_k4]
            uint32_t b0[2] = {bq0.x, bq0.z};
            uint32_t b1[2] = {bq0.y, bq0.w};
            uint32_t b2[2] = {bq1.x, bq1.z};
            uint32_t b3[2] = {bq1.y, bq1.w};
#pragma unroll
            for (int i = 0; i < 3; i++) {
                const uint4 aq = *reinterpret_cast<const uint4*>(
                    &sA[i * 1024 + abase + ko]);
                uint32_t a[4] = {aq.x, aq.y, aq.z, aq.w};  // [rq_k, rq8_k, rq_k4, rq8_k4]
                mma8(acc[i][0], a, b0);
                mma8(acc[i][1], a, b1);
                mma8(acc[i][2], a, b2);
                mma8(acc[i][3], a, b3);
            }
        }
        buf = (buf + 1 >= NSTAGE) ? 0 : buf + 1;
    }

    // ---- epilogue: out1 (1o->1o), interleaved layout, vectorized float2
    const float sc = 0.04419417382415922f;  // 1/sqrt(512)
    {
        const int r  = tt0 + warp_t * 16 + q;
        const int wc = w0 + warp_w * 32 + 2 * rr;
#pragma unroll
        for (int nt = 0; nt < 4; nt++) {
            const int w = wc + nt * 8;
            float* p  = out + (size_t)r * OUTW + 512 + 3 * w;
            float* p2 = p + (size_t)8 * OUTW;
            float2 v;
            v = make_float2(acc[0][nt][0] * sc, acc[1][nt][0] * sc); *reinterpret_cast<float2*>(p + 0) = v;
            v = make_float2(acc[2][nt][0] * sc, acc[0][nt][1] * sc); *reinterpret_cast<float2*>(p + 2) = v;
            v = make_float2(acc[1][nt][1] * sc, acc[2][nt][1] * sc); *reinterpret_cast<float2*>(p + 4) = v;
            v = make_float2(acc[0][nt][2] * sc, acc[1][nt][2] * sc); *reinterpret_cast<float2*>(p2 + 0) = v;
            v = make_float2(acc[2][nt][2] * sc, acc[0][nt][3] * sc); *reinterpret_cast<float2*>(p2 + 2) = v;
            v = make_float2(acc[1][nt][3] * sc, acc[2][nt][3] * sc); *reinterpret_cast<float2*>(p2 + 4) = v;
        }
    }

    // ---- epilogue: out0 (0e->0e), cols [w0, w0+128)
    {
        const float k3 = 0.5773502691896258f;  // 1/sqrt(3)
        const int r  = tid >> 3;               // 0..31
        const int cb = (tid & 7) * 16;
        const float s0 = sS[r * 3 + 0], s1 = sS[r * 3 + 1], s2 = sS[r * 3 + 2];
        float* po = out + (size_t)(tt0 + r) * OUTW + w0 + cb;
#pragma unroll
        for (int jj = 0; jj < 16; jj += 4) {
            float4 v;
            v.x = (s0 * sW0[cb + jj + 0] + s1 * sW0[128 + cb + jj + 0] + s2 * sW0[256 + cb + jj + 0]) * k3;
            v.y = (s0 * sW0[cb + jj + 1] + s1 * sW0[128 + cb + jj + 1] + s2 * sW0[256 + cb + jj + 1]) * k3;
            v.z = (s0 * sW0[cb + jj + 2] + s1 * sW0[128 + cb + jj + 2] + s2 * sW0[256 + cb + jj + 2]) * k3;
            v.w = (s0 * sW0[cb + jj + 3] + s1 * sW0[128 + cb + jj + 3] + s2 * sW0[256 + cb + jj + 3]) * k3;
            *reinterpret_cast<float4*>(po + jj) = v;
        }
    }
}

extern "C" void kernel_launch(void* const* d_in, const int* in_sizes, int n_in,
                              void* d_out, int out_size) {
    const float* V  = nullptr;   // vectors [4,2048,1536] = 12582912
    const float* S  = nullptr;   // scalars [4,2048,3]    = 24576
    const float* W0 = nullptr;   // [3,512]               = 1536
    const float* W1 = nullptr;   // [512,512]             = 262144
    for (int i = 0; i < n_in; i++) {
        switch (in_sizes[i]) {
            case 12582912: V  = (const float*)d_in[i]; break;
            case 24576:    S  = (const float*)d_in[i]; break;
            case 1536:     W0 = (const float*)d_in[i]; break;
            case 262144:   W1 = (const float*)d_in[i]; break;
            default: break;
        }
    }
    float* out = (float*)d_out;

    pre_all<<<4224, 512>>>(V, W1);

    cudaFuncSetAttribute(fused, cudaFuncAttributeMaxDynamicSharedMemorySize, DYN_SMEM);
    dim3 grid(MULT / BW, T_TOT / BT);   // (4, 256) = 1024 CTAs
    fused<<<grid, NTHR, DYN_SMEM>>>(S, W0, out);
}

// round 16
// speedup vs baseline: 1.0014x; 1.0014x over previous
#include <cuda_runtime.h>
#include <cstdint>
#include <cstddef>

#define T_TOT 8192
#define MULT  512
#define OUTW  8192
#define VROW  1536

#define BT 32
#define BW 128
#define NTHR 256
#define NITER 16

#define A_STAGE_W (3*BT*32)           // 3072 words
#define B_STAGE_W (BW*32)             // 4096 words
#define STAGE_W   (A_STAGE_W + B_STAGE_W)   // 7168
#define NSTAGE 3
#define DYN_SMEM  (NSTAGE*STAGE_W*4)  // 86016 bytes -> 2 CTAs/SM

#define VPLANE (T_TOT*MULT)

// ---- scratch (static device globals: allowed; no runtime allocation)
__device__ uint32_t g_Vd[3u * VPLANE];        // tf32 bits, [i][t][perm word]
__device__ uint32_t g_W1t[MULT * MULT];       // tf32 bits, [n][perm word]

static __device__ __forceinline__ uint32_t smem_u32(const void* p) {
    uint32_t r;
    asm("{ .reg .u64 t; cvta.to.shared.u64 t, %1; cvt.u32.u64 %0, t; }" : "=r"(r) : "l"(p));
    return r;
}
static __device__ __forceinline__ uint32_t f2tf(float x) {
    uint32_t r; asm("cvt.rna.tf32.f32 %0, %1;" : "=r"(r) : "f"(x)); return r;
}
// conflict-free stored word for logical u (within 32-chunk) at matrix row `row`:
//   u = 8*g + 4*h + c  ->  word = 8*c + 2*((g + row) & 3) + h
static __device__ __forceinline__ int permw(int uu, int row) {
    const int g = uu >> 3, h = (uu >> 2) & 1, c = uu & 3;
    return 8 * c + 2 * ((g + row) & 3) + h;
}
static __device__ __forceinline__ void cpa16(uint32_t dst, const void* src) {
    asm volatile("cp.async.cg.shared.global [%0], [%1], 16;" :: "r"(dst), "l"(src));
}
// streaming (evict-first) output stores: output is write-once, never re-read
static __device__ __forceinline__ void stg_cs_v4(float* p, float x, float y, float z, float w) {
    asm volatile("st.global.cs.v4.f32 [%0], {%1,%2,%3,%4};"
                 :: "l"(p), "f"(x), "f"(y), "f"(z), "f"(w) : "memory");
}
static __device__ __forceinline__ void stg_cs_v2(float* p, float x, float y) {
    asm volatile("st.global.cs.v2.f32 [%0], {%1,%2};"
                 :: "l"(p), "f"(x), "f"(y) : "memory");
}
static __device__ __forceinline__ void mma8(float* c, const uint32_t* a, const uint32_t* b) {
    asm volatile(
        "mma.sync.aligned.m16n8k8.row.col.f32.tf32.tf32.f32 "
        "{%0,%1,%2,%3},{%4,%5,%6,%7},{%8,%9},{%0,%1,%2,%3};\n"
        : "+f"(c[0]), "+f"(c[1]), "+f"(c[2]), "+f"(c[3])
        : "r"(a[0]), "r"(a[1]), "r"(a[2]), "r"(a[3]),
          "r"(b[0]), "r"(b[1]));
}

// ---- merged pre-kernel: blocks [0,2048) de-interleave V; blocks [2048,2176) transpose W1
__global__ void __launch_bounds__(512, 2)
pre_all(const float* __restrict__ V, const float* __restrict__ W1) {
    __shared__ float sbuf[4 * VROW];              // V: 4 token rows; W: aliased 2 tiles
    const int tid = threadIdx.x;

    if (blockIdx.x < 2048) {
        // ---- V part: [t][3u+i] -> g_Vd[i][t][chunk*32 + permw], STG.64 pairs
        const int r0 = blockIdx.x * 4;
        const float4* v4 = reinterpret_cast<const float4*>(V) + (size_t)r0 * 384;
#pragma unroll
        for (int k = 0; k < 3; k++) {
            const int c = tid + k * 512;
            const float4 d = v4[c];
            float* sp = sbuf + 4 * c;
            sp[0] = d.x; sp[1] = d.y; sp[2] = d.z; sp[3] = d.w;
        }
        __syncthreads();
        const int half = tid >> 8;                 // 0..1 -> rows {0,1} or {2,3}
        const int P = tid & 255;                   // pair id
        const int c32 = P >> 4, g = (P >> 2) & 3, c = P & 3;
        const int u1 = c32 * 32 + 8 * g + c;       // h=0; u2 = u1+4 (h=1)
#pragma unroll
        for (int rr2 = 0; rr2 < 2; rr2++) {
            const int r = half * 2 + rr2;
            const int t = r0 + r;
            const int w = c32 * 32 + 8 * c + 2 * ((g + t) & 3);
            const float* sp = sbuf + r * VROW + 3 * u1;
            const size_t o = (size_t)t * 512 + w;
            *(uint2*)&g_Vd[o]              = make_uint2(f2tf(sp[0]), f2tf(sp[12]));
            *(uint2*)&g_Vd[o + VPLANE]     = make_uint2(f2tf(sp[1]), f2tf(sp[13]));
            *(uint2*)&g_Vd[o + 2 * VPLANE] = make_uint2(f2tf(sp[2]), f2tf(sp[14]));
        }
    } else {
        // ---- W part: W1 [u][n] -> g_W1t[n][bu + permw(u%32, n)], 2 tiles per block
        float (*wt)[32][33] = reinterpret_cast<float (*)[32][33]>(sbuf);
        const int h = tid >> 8;                    // which tile
        const int t256 = tid & 255;
        const int tx = t256 & 31, ty = t256 >> 5;  // (32, 8)
        const int tile = (blockIdx.x - 2048) * 2 + h;
        const int bn = (tile & 15) * 32, bu = (tile >> 4) * 32;
#pragma unroll
        for (int j = 0; j < 32; j += 8)
            wt[h][ty + j][tx] = W1[(size_t)(bu + ty + j) * MULT + bn + tx];
        __syncthreads();
#pragma unroll
        for (int j = 0; j < 32; j += 8) {
            const int n = bn + ty + j;
            g_W1t[(size_t)n * 512 + bu + permw(tx, n)] = f2tf(wt[h][tx][ty + j]);
        }
    }
}

// ---- main fused kernel (R12 winner): CTA 32x128, warp 16x32x3, 2 CTAs/SM
__global__ void __launch_bounds__(NTHR, 2)
fused(const float* __restrict__ S, const float* __restrict__ W0,
      float* __restrict__ out)
{
    extern __shared__ uint32_t dsm[];
    __shared__ float sS[96];
    __shared__ float sW0[384];

    const int tid  = threadIdx.x;
    const int lane = tid & 31;
    const int wid  = tid >> 5;
    const int q  = lane >> 2;          // 0..7
    const int rr = lane & 3;           // 0..3
    const int warp_t = wid >> 2;       // 0..1 -> rows warp_t*16
    const int warp_w = wid & 3;        // 0..3 -> cols warp_w*32
    const int bx = blockIdx.x, by = blockIdx.y;
    const int tt0 = by * BT, w0 = bx * BW;

    if (tid < 96)  sS[tid]  = S[(size_t)tt0 * 3 + tid];
    sW0[tid] = W0[(tid >> 7) * 512 + w0 + (tid & 127)];
    if (tid < 128) sW0[256 + tid] = W0[1024 + w0 + tid];

    // ---- cp.async staging addresses (loop-invariant)
    const uint32_t smem0 = smem_u32(dsm);
    uint32_t aDst[3]; const uint32_t* aSrc[3];
#pragma unroll
    for (int s = 0; s < 3; s++) {
        const int c = tid + s * NTHR;          // 0..767 (3 planes x 32 t x 8 chunks)
        const int i = c >> 8, rem = c & 255;
        const int t = rem >> 3, j = rem & 7;
        aDst[s] = smem0 + (i * (BT * 32) + t * 32 + 4 * j) * 4;
        aSrc[s] = g_Vd + (size_t)i * VPLANE + (size_t)(tt0 + t) * 512 + 4 * j;
    }
    uint32_t bDst[4]; const uint32_t* bSrc[4];
#pragma unroll
    for (int s = 0; s < 4; s++) {
        const int c = tid + s * NTHR;          // 0..1023 (128 n x 8 chunks)
        const int n = c >> 3, j = c & 7;
        bDst[s] = smem0 + (A_STAGE_W + n * 32 + 4 * j) * 4;
        bSrc[s] = g_W1t + (size_t)(w0 + n) * 512 + 4 * j;
    }

#define STAGE(K, BUF) do {                                                  \
        const uint32_t off_ = (BUF) * (STAGE_W * 4);                        \
        const int kw_ = (K) * 32;                                          \
        _Pragma("unroll")                                                   \
        for (int s_ = 0; s_ < 3; s_++) cpa16(aDst[s_] + off_, aSrc[s_] + kw_); \
        _Pragma("unroll")                                                   \
        for (int s_ = 0; s_ < 4; s_++) cpa16(bDst[s_] + off_, bSrc[s_] + kw_); \
        asm volatile("cp.async.commit_group;" ::: "memory");                \
    } while (0)

    float acc[3][4][4];
#pragma unroll
    for (int i = 0; i < 3; i++)
#pragma unroll
        for (int n = 0; n < 4; n++)
#pragma unroll
            for (int r = 0; r < 4; r++) acc[i][n][r] = 0.f;

    STAGE(0, 0);
    STAGE(1, 1);

    int buf = 0;
    for (int it = 0; it < NITER; ++it) {
        if (it == NITER - 1) asm volatile("cp.async.wait_group 0;" ::: "memory");
        else                 asm volatile("cp.async.wait_group 1;" ::: "memory");
        __syncthreads();

        if (it + 2 < NITER) {
            const int nb = (buf + 2 >= NSTAGE) ? buf + 2 - NSTAGE : buf + 2;
            STAGE(it + 2, nb);
        }

        // ---- stream the exact-zero block (2 rows x 384 quads/iter, evict-streaming)
        {
            const int r = 2 * it + (tid >> 7);
            const int c = (tid & 127) * 3;
            float* zp = out + ((size_t)(tt0 + r) * 2048 + 512 + 384 * bx + c) * 4;
            stg_cs_v4(zp + 0, 0.f, 0.f, 0.f, 0.f);
            stg_cs_v4(zp + 4, 0.f, 0.f, 0.f, 0.f);
            stg_cs_v4(zp + 8, 0.f, 0.f, 0.f, 0.f);
        }

        // ---- compute 4 k8-steps (conflict-free LDS.64 everywhere)
        const uint32_t* sA = dsm + buf * STAGE_W;
        const uint32_t* sB = sA + A_STAGE_W;
        const int arow = (warp_t * 16 + q) * 32;
#pragma unroll
        for (int g = 0; g < 4; g++) {
            const int koff = 8 * rr + 2 * ((g + q) & 3);   // same for A rows & B cols
            uint32_t b[4][2];
#pragma unroll
            for (int nt = 0; nt < 4; nt++) {
                const int n = warp_w * 32 + nt * 8 + q;
                const uint2 bb = *reinterpret_cast<const uint2*>(&sB[n * 32 + koff]);
                b[nt][0] = bb.x; b[nt][1] = bb.y;     // k = 8g+rr, 8g+rr+4
            }
#pragma unroll
            for (int i = 0; i < 3; i++) {
                const uint32_t* ap = sA + i * (BT * 32) + arow + koff;
                const uint2 alo = *reinterpret_cast<const uint2*>(ap);        // row q
                const uint2 ahi = *reinterpret_cast<const uint2*>(ap + 256);  // row q+8
                uint32_t a[4] = {alo.x, ahi.x, alo.y, ahi.y};
#pragma unroll
                for (int nt = 0; nt < 4; nt++) mma8(acc[i][nt], a, b[nt]);
            }
        }
        buf = (buf + 1 >= NSTAGE) ? 0 : buf + 1;
    }

    // ---- epilogue: out1 (1o->1o), interleaved layout, streaming float2 stores
    const float sc = 0.04419417382415922f;  // 1/sqrt(512)
    {
        const int r  = tt0 + warp_t * 16 + q;
        const int wc = w0 + warp_w * 32 + 2 * rr;
#pragma unroll
        for (int nt = 0; nt < 4; nt++) {
            const int w = wc + nt * 8;
            float* p  = out + (size_t)r * OUTW + 512 + 3 * w;
            float* p2 = p + (size_t)8 * OUTW;
            stg_cs_v2(p + 0,  acc[0][nt][0] * sc, acc[1][nt][0] * sc);
            stg_cs_v2(p + 2,  acc[2][nt][0] * sc, acc[0][nt][1] * sc);
            stg_cs_v2(p + 4,  acc[1][nt][1] * sc, acc[2][nt][1] * sc);
            stg_cs_v2(p2 + 0, acc[0][nt][2] * sc, acc[1][nt][2] * sc);
            stg_cs_v2(p2 + 2, acc[2][nt][2] * sc, acc[0][nt][3] * sc);
            stg_cs_v2(p2 + 4, acc[1][nt][3] * sc, acc[2][nt][3] * sc);
        }
    }

    // ---- epilogue: out0 (0e->0e), cols [w0, w0+128), streaming float4 stores
    {
        const float k3 = 0.5773502691896258f;  // 1/sqrt(3)
        const int r  = tid >> 3;               // 0..31
        const int cb = (tid & 7) * 16;
        const float s0 = sS[r * 3 + 0], s1 = sS[r * 3 + 1], s2 = sS[r * 3 + 2];
        float* po = out + (size_t)(tt0 + r) * OUTW + w0 + cb;
#pragma unroll
        for (int jj = 0; jj < 16; jj += 4) {
            stg_cs_v4(po + jj,
                (s0 * sW0[cb + jj + 0] + s1 * sW0[128 + cb + jj + 0] + s2 * sW0[256 + cb + jj + 0]) * k3,
                (s0 * sW0[cb + jj + 1] + s1 * sW0[128 + cb + jj + 1] + s2 * sW0[256 + cb + jj + 1]) * k3,
                (s0 * sW0[cb + jj + 2] + s1 * sW0[128 + cb + jj + 2] + s2 * sW0[256 + cb + jj + 2]) * k3,
                (s0 * sW0[cb + jj + 3] + s1 * sW0[128 + cb + jj + 3] + s2 * sW0[256 + cb + jj + 3]) * k3);
        }
    }
}

extern "C" void kernel_launch(void* const* d_in, const int* in_sizes, int n_in,
                              void* d_out, int out_size) {
    const float* V  = nullptr;   // vectors [4,2048,1536] = 12582912
    const float* S  = nullptr;   // scalars [4,2048,3]    = 24576
    const float* W0 = nullptr;   // [3,512]               = 1536
    const float* W1 = nullptr;   // [512,512]             = 262144
    for (int i = 0; i < n_in; i++) {
        switch (in_sizes[i]) {
            case 12582912: V  = (const float*)d_in[i]; break;
            case 24576:    S  = (const float*)d_in[i]; break;
            case 1536:     W0 = (const float*)d_in[i]; break;
            case 262144:   W1 = (const float*)d_in[i]; break;
            default: break;
        }
    }
    float* out = (float*)d_out;

    pre_all<<<2176, 512>>>(V, W1);

    cudaFuncSetAttribute(fused, cudaFuncAttributeMaxDynamicSharedMemorySize, DYN_SMEM);
    dim3 grid(MULT / BW, T_TOT / BT);   // (4, 256) = 1024 CTAs
    fused<<<grid, NTHR, DYN_SMEM>>>(S, W0, out);
}

// round 17
// speedup vs baseline: 1.2264x; 1.2247x over previous
#include <cuda_runtime.h>
#include <cuda_fp16.h>
#include <cstdint>
#include <cstddef>

#define T_TOT 8192
#define MULT  512
#define OUTW  8192
#define VROW  1536

#define BT 32
#define BW 128
#define NTHR 256
#define NITER 16                      // k-chunk = 32

#define ROWW 24                       // smem words per row (16 data + 8 pad) = 96B
#define A_STAGE_W (3*BT*ROWW)         // 2304 words
#define B_STAGE_W (BW*ROWW)           // 3072 words
#define STAGE_W   (A_STAGE_W + B_STAGE_W)   // 5376 words = 21504B
#define NSTAGE 3
#define DYN_SMEM  (NSTAGE*STAGE_W*4)  // 64512 B -> 2 CTAs/SM

#define VPW (T_TOT*256)               // words per V plane (half2-packed)

// ---- scratch (static device globals: allowed; no runtime allocation)
// word layout per row, per 16-word k32 chunk (word = half2 = k-pair):
//   pair m (0..15): w16 = 8*(m>>3) + 2*(m&3) + ((m>>2)&1)
//   -> fragment pairs (rr, rr+4) of each k16 step are adjacent words
__device__ uint32_t g_Vh[3u * VPW];           // fp16x2, [i][t][chunk][w16]
__device__ uint32_t g_W1h[MULT * 256];        // fp16x2, [n][chunk][w16]

static __device__ __forceinline__ uint32_t smem_u32(const void* p) {
    uint32_t r;
    asm("{ .reg .u64 t; cvta.to.shared.u64 t, %1; cvt.u32.u64 %0, t; }" : "=r"(r) : "l"(p));
    return r;
}
static __device__ __forceinline__ uint32_t pk(float lo, float hi) {
    __half2 h = __floats2half2_rn(lo, hi);
    return *reinterpret_cast<uint32_t*>(&h);
}
static __device__ __forceinline__ void cpa16(uint32_t dst, const void* src) {
    asm volatile("cp.async.cg.shared.global [%0], [%1], 16;" :: "r"(dst), "l"(src));
}
static __device__ __forceinline__ void stg_cs_v4(float* p, float x, float y, float z, float w) {
    asm volatile("st.global.cs.v4.f32 [%0], {%1,%2,%3,%4};"
                 :: "l"(p), "f"(x), "f"(y), "f"(z), "f"(w) : "memory");
}
static __device__ __forceinline__ void stg_cs_v2(float* p, float x, float y) {
    asm volatile("st.global.cs.v2.f32 [%0], {%1,%2};"
                 :: "l"(p), "f"(x), "f"(y) : "memory");
}
static __device__ __forceinline__ void mma16(float* c, const uint32_t* a, const uint32_t* b) {
    asm volatile(
        "mma.sync.aligned.m16n8k16.row.col.f32.f16.f16.f32 "
        "{%0,%1,%2,%3},{%4,%5,%6,%7},{%8,%9},{%0,%1,%2,%3};\n"
        : "+f"(c[0]), "+f"(c[1]), "+f"(c[2]), "+f"(c[3])
        : "r"(a[0]), "r"(a[1]), "r"(a[2]), "r"(a[3]),
          "r"(b[0]), "r"(b[1]));
}
static __device__ __forceinline__ int w16of(int m) {   // pair index 0..15 -> word
    return 8 * (m >> 3) + 2 * (m & 3) + ((m >> 2) & 1);
}

// ---- merged pre-kernel: blocks [0,2048) de-interleave V; blocks [2048,2176) transpose W1
__global__ void __launch_bounds__(512, 2)
pre_all(const float* __restrict__ V, const float* __restrict__ W1) {
    __shared__ float sbuf[4 * VROW];              // V: 4 token rows; W: aliased 2 tiles
    const int tid = threadIdx.x;

    if (blockIdx.x < 2048) {
        // ---- V: [t][3u+i] -> g_Vh planes, half2 k-pairs
        const int r0 = blockIdx.x * 4;
        const float4* v4 = reinterpret_cast<const float4*>(V) + (size_t)r0 * 384;
#pragma unroll
        for (int k = 0; k < 3; k++) {
            const int c = tid + k * 512;
            const float4 d = v4[c];
            float* sp = sbuf + 4 * c;
            sp[0] = d.x; sp[1] = d.y; sp[2] = d.z; sp[3] = d.w;
        }
        __syncthreads();
        const int half = tid >> 8;                 // rows {0,1} or {2,3}
        const int m = tid & 255;                   // k-pair index 0..255
        const int w = (m >> 4) * 16 + w16of(m & 15);
#pragma unroll
        for (int rr2 = 0; rr2 < 2; rr2++) {
            const int r = half * 2 + rr2;
            const int t = r0 + r;
            const float* sp = sbuf + r * VROW + 6 * m;   // u=2m (even), 2m+1 at +3
            const size_t o = (size_t)t * 256 + w;
            g_Vh[o]           = pk(sp[0], sp[3]);
            g_Vh[o + VPW]     = pk(sp[1], sp[4]);
            g_Vh[o + 2 * VPW] = pk(sp[2], sp[5]);
        }
    } else {
        // ---- W: W1 [u][n] -> g_W1h [n][k-pair words], 2 tiles (32x32) per block
        float (*wt)[32][33] = reinterpret_cast<float (*)[32][33]>(sbuf);
        const int h = tid >> 8;
        const int t256 = tid & 255;
        const int tx = t256 & 31, ty = t256 >> 5;  // (32, 8)
        const int tile = (blockIdx.x - 2048) * 2 + h;
        const int bn = (tile & 15) * 32, bu = (tile >> 4) * 32;
#pragma unroll
        for (int j = 0; j < 32; j += 8)
            wt[h][ty + j][tx] = W1[(size_t)(bu + ty + j) * MULT + bn + tx];
        __syncthreads();
        if (tx < 16) {
            const int P = (bu >> 1) + tx;          // global u-pair index
            const int w = (P >> 4) * 16 + w16of(P & 15);
#pragma unroll
            for (int j = 0; j < 32; j += 8) {
                const int nl = ty + j;
                g_W1h[(size_t)(bn + nl) * 256 + w] =
                    pk(wt[h][2 * tx][nl], wt[h][2 * tx + 1][nl]);
            }
        }
    }
}

// ---- main fused kernel: CTA 32x128, warp 16x32x3, fp16 m16n8k16, 2 CTAs/SM
__global__ void __launch_bounds__(NTHR, 2)
fused(const float* __restrict__ S, const float* __restrict__ W0,
      float* __restrict__ out)
{
    extern __shared__ uint32_t dsm[];
    __shared__ float sS[96];
    __shared__ float sW0[384];

    const int tid  = threadIdx.x;
    const int lane = tid & 31;
    const int wid  = tid >> 5;
    const int q  = lane >> 2;          // 0..7
    const int rr = lane & 3;           // 0..3
    const int warp_t = wid >> 2;       // 0..1 -> rows warp_t*16
    const int warp_w = wid & 3;        // 0..3 -> cols warp_w*32
    const int bx = blockIdx.x, by = blockIdx.y;
    const int tt0 = by * BT, w0 = bx * BW;

    if (tid < 96)  sS[tid]  = S[(size_t)tt0 * 3 + tid];
    sW0[tid] = W0[(tid >> 7) * 512 + w0 + (tid & 127)];
    if (tid < 128) sW0[256 + tid] = W0[1024 + w0 + tid];

    // ---- cp.async staging: 896 16B chunks/stage; chunks c<384 = A, else B
    const uint32_t smem0 = smem_u32(dsm);
    uint32_t sDst[4]; const uint32_t* sSrc[4];
#pragma unroll
    for (int s = 0; s < 4; s++) {
        const int c = (s < 3) ? (tid + s * NTHR) : (768 + tid);  // s=3: tid<128 only
        if (c < 384) {
            const int i = c / 128, rem = c % 128;
            const int row = rem >> 2, jc = rem & 3;
            sDst[s] = smem0 + (i * (BT * ROWW) + row * ROWW + jc * 4) * 4;
            sSrc[s] = g_Vh + (size_t)i * VPW + (size_t)(tt0 + row) * 256 + jc * 4;
        } else {
            const int cb = c - 384;
            const int n = cb >> 2, jc = cb & 3;
            sDst[s] = smem0 + (A_STAGE_W + n * ROWW + jc * 4) * 4;
            sSrc[s] = g_W1h + (size_t)(w0 + n) * 256 + jc * 4;
        }
    }
    const bool has4 = (tid < 128);

#define STAGE(K, BUF) do {                                                   \
        const uint32_t off_ = (BUF) * (STAGE_W * 4);                         \
        const int kw_ = (K) * 16;                                            \
        cpa16(sDst[0] + off_, sSrc[0] + kw_);                                \
        cpa16(sDst[1] + off_, sSrc[1] + kw_);                                \
        cpa16(sDst[2] + off_, sSrc[2] + kw_);                                \
        if (has4) cpa16(sDst[3] + off_, sSrc[3] + kw_);                      \
        asm volatile("cp.async.commit_group;" ::: "memory");                 \
    } while (0)

    float acc[3][4][4];
#pragma unroll
    for (int i = 0; i < 3; i++)
#pragma unroll
        for (int n = 0; n < 4; n++)
#pragma unroll
            for (int r = 0; r < 4; r++) acc[i][n][r] = 0.f;

    STAGE(0, 0);
    STAGE(1, 1);

    const int arow = (warp_t * 16 + q) * ROWW;
    const int brow = (warp_w * 32 + q) * ROWW;

    int buf = 0;
    for (int it = 0; it < NITER; ++it) {
        if (it == NITER - 1) asm volatile("cp.async.wait_group 0;" ::: "memory");
        else                 asm volatile("cp.async.wait_group 1;" ::: "memory");
        __syncthreads();

        if (it + 2 < NITER) {
            const int nb = (buf + 2 >= NSTAGE) ? buf + 2 - NSTAGE : buf + 2;
            STAGE(it + 2, nb);
        }

        // ---- stream the exact-zero block (2 rows x 384 quads/iter, evict-streaming)
        {
            const int r = 2 * it + (tid >> 7);
            const int c = (tid & 127) * 3;
            float* zp = out + ((size_t)(tt0 + r) * 2048 + 512 + 384 * bx + c) * 4;
            stg_cs_v4(zp + 0, 0.f, 0.f, 0.f, 0.f);
            stg_cs_v4(zp + 4, 0.f, 0.f, 0.f, 0.f);
            stg_cs_v4(zp + 8, 0.f, 0.f, 0.f, 0.f);
        }

        // ---- compute 2 k16-steps (all LDS.64 conflict-free via 96B row stride)
        const uint32_t* sA = dsm + buf * STAGE_W;
        const uint32_t* sB = sA + A_STAGE_W;
#pragma unroll
        for (int s = 0; s < 2; s++) {
            const int koff = 8 * s + 2 * rr;
            uint32_t b[4][2];
#pragma unroll
            for (int nt = 0; nt < 4; nt++) {
                const uint2 bb = *reinterpret_cast<const uint2*>(
                    &sB[brow + nt * (8 * ROWW) + koff]);
                b[nt][0] = bb.x; b[nt][1] = bb.y;      // pairs rr, rr+4
            }
#pragma unroll
            for (int i = 0; i < 3; i++) {
                const uint32_t* ap = sA + i * (BT * ROWW) + arow + koff;
                const uint2 alo = *reinterpret_cast<const uint2*>(ap);             // row q
                const uint2 ahi = *reinterpret_cast<const uint2*>(ap + 8 * ROWW);  // row q+8
                uint32_t a[4] = {alo.x, ahi.x, alo.y, ahi.y};
#pragma unroll
                for (int nt = 0; nt < 4; nt++) mma16(acc[i][nt], a, b[nt]);
            }
        }
        buf = (buf + 1 >= NSTAGE) ? 0 : buf + 1;
    }

    // ---- epilogue: out1 (1o->1o), interleaved layout, streaming float2 stores
    const float sc = 0.04419417382415922f;  // 1/sqrt(512)
    {
        const int r  = tt0 + warp_t * 16 + q;
        const int wc = w0 + warp_w * 32 + 2 * rr;
#pragma unroll
        for (int nt = 0; nt < 4; nt++) {
            const int w = wc + nt * 8;
            float* p  = out + (size_t)r * OUTW + 512 + 3 * w;
            float* p2 = p + (size_t)8 * OUTW;
            stg_cs_v2(p + 0,  acc[0][nt][0] * sc, acc[1][nt][0] * sc);
            stg_cs_v2(p + 2,  acc[2][nt][0] * sc, acc[0][nt][1] * sc);
            stg_cs_v2(p + 4,  acc[1][nt][1] * sc, acc[2][nt][1] * sc);
            stg_cs_v2(p2 + 0, acc[0][nt][2] * sc, acc[1][nt][2] * sc);
            stg_cs_v2(p2 + 2, acc[2][nt][2] * sc, acc[0][nt][3] * sc);
            stg_cs_v2(p2 + 4, acc[1][nt][3] * sc, acc[2][nt][3] * sc);
        }
    }

    // ---- epilogue: out0 (0e->0e), cols [w0, w0+128), fp32 math (exact path)
    {
        const float k3 = 0.5773502691896258f;  // 1/sqrt(3)
        const int r  = tid >> 3;               // 0..31
        const int cb = (tid & 7) * 16;
        const float s0 = sS[r * 3 + 0], s1 = sS[r * 3 + 1], s2 = sS[r * 3 + 2];
        float* po = out + (size_t)(tt0 + r) * OUTW + w0 + cb;
#pragma unroll
        for (int jj = 0; jj < 16; jj += 4) {
            stg_cs_v4(po + jj,
                (s0 * sW0[cb + jj + 0] + s1 * sW0[128 + cb + jj + 0] + s2 * sW0[256 + cb + jj + 0]) * k3,
                (s0 * sW0[cb + jj + 1] + s1 * sW0[128 + cb + jj + 1] + s2 * sW0[256 + cb + jj + 1]) * k3,
                (s0 * sW0[cb + jj + 2] + s1 * sW0[128 + cb + jj + 2] + s2 * sW0[256 + cb + jj + 2]) * k3,
                (s0 * sW0[cb + jj + 3] + s1 * sW0[128 + cb + jj + 3] + s2 * sW0[256 + cb + jj + 3]) * k3);
        }
    }
}

extern "C" void kernel_launch(void* const* d_in, const int* in_sizes, int n_in,
                              void* d_out, int out_size) {
    const float* V  = nullptr;   // vectors [4,2048,1536] = 12582912
    const float* S  = nullptr;   // scalars [4,2048,3]    = 24576
    const float* W0 = nullptr;   // [3,512]               = 1536
    const float* W1 = nullptr;   // [512,512]             = 262144
    for (int i = 0; i < n_in; i++) {
        switch (in_sizes[i]) {
            case 12582912: V  = (const float*)d_in[i]; break;
            case 24576:    S  = (const float*)d_in[i]; break;
            case 1536:     W0 = (const float*)d_in[i]; break;
            case 262144:   W1 = (const float*)d_in[i]; break;
            default: break;
        }
    }
    float* out = (float*)d_out;

    pre_all<<<2176, 512>>>(V, W1);

    cudaFuncSetAttribute(fused, cudaFuncAttributeMaxDynamicSharedMemorySize, DYN_SMEM);
    dim3 grid(MULT / BW, T_TOT / BT);   // (4, 256) = 1024 CTAs
    fused<<<grid, NTHR, DYN_SMEM>>>(S, W0, out);
}